// round 1
// baseline (speedup 1.0000x reference)
#include <cuda_runtime.h>
#include <cstdint>
#include <math.h>

#define NN 30000
#define KK 15
#define TT 400
#define NCC 5
#define GG 8                 // rows per block in main kernel (30000 % 8 == 0)
#define ROWS 16              // self + 15 neighbors
#define ROWBYTES (TT * 4)    // 1600 B per row
#define STAGEBYTES (ROWS * ROWBYTES)  // 25600 B
#define T4 (TT / 4)          // 100 float4 per row

// ---------------- scratch (device globals: allocation-free) ----------------
__device__ float g_emd[NN * TT];        // summed EMD signals [N,T]  (48 MB)
__device__ float g_W[NN * 16];          // [0]=self weight (1-ew), [1..15]=combined neighbor weights
__device__ float g_UV[NN * 10];         // u[5] (coeff of sin(wt)), v[5] (coeff of cos(wt))
__device__ float g_tab[2 * NCC * TT];   // sin table [5*400], then cos table [5*400]

// ---------------- helpers ----------------
__device__ __forceinline__ uint32_t smem_u32(const void* p) {
    uint32_t a;
    asm("{ .reg .u64 t; cvta.to.shared.u64 t, %1; cvt.u32.u64 %0, t; }"
        : "=r"(a) : "l"(p));
    return a;
}

__device__ __forceinline__ void mbar_init(uint32_t mbar, uint32_t count) {
    asm volatile("mbarrier.init.shared.b64 [%0], %1;" :: "r"(mbar), "r"(count) : "memory");
}

__device__ __forceinline__ void mbar_expect_tx(uint32_t mbar, uint32_t bytes) {
    asm volatile("mbarrier.arrive.expect_tx.shared.b64 _, [%0], %1;"
                 :: "r"(mbar), "r"(bytes) : "memory");
}

__device__ __forceinline__ void mbar_wait(uint32_t mbar, uint32_t parity) {
    asm volatile(
        "{\n\t"
        ".reg .pred P;\n\t"
        "LAB_WAIT_%=:\n\t"
        "mbarrier.try_wait.parity.acquire.cta.shared::cta.b64 P, [%0], %1, 0x989680;\n\t"
        "@P bra LAB_DONE_%=;\n\t"
        "bra LAB_WAIT_%=;\n\t"
        "LAB_DONE_%=:\n\t"
        "}"
        :: "r"(mbar), "r"(parity) : "memory");
}

__device__ __forceinline__ void bulk_g2s(uint32_t dst, const void* src,
                                         uint32_t bytes, uint32_t mbar) {
    asm volatile(
        "cp.async.bulk.shared::cluster.global.mbarrier::complete_tx::bytes "
        "[%0], [%1], %2, [%3];"
        :: "r"(dst), "l"(src), "r"(bytes), "r"(mbar) : "memory");
}

// ---------------- kernel: sum 4 EMD components -> g_emd ----------------
__global__ void k_emdsum(const float* __restrict__ emd) {
    int i = blockIdx.x * blockDim.x + threadIdx.x;
    if (i >= NN * T4) return;
    int n = i / T4;
    int t4 = i - n * T4;
    const float4* b = reinterpret_cast<const float4*>(emd + (size_t)n * 4 * TT);
    float4 a0 = b[0 * T4 + t4];
    float4 a1 = b[1 * T4 + t4];
    float4 a2 = b[2 * T4 + t4];
    float4 a3 = b[3 * T4 + t4];
    float4 r;
    r.x = (a0.x + a1.x) + (a2.x + a3.x);
    r.y = (a0.y + a1.y) + (a2.y + a3.y);
    r.z = (a0.z + a1.z) + (a2.z + a3.z);
    r.w = (a0.w + a1.w) + (a2.w + a3.w);
    reinterpret_cast<float4*>(g_emd + (size_t)n * TT)[t4] = r;
}

// ---------------- kernel: combined spatial weights -> g_W ----------------
__global__ void k_weights(const float* __restrict__ nbr_w,
                          const float* __restrict__ loc_w,
                          const float* __restrict__ esw,
                          const float* __restrict__ lsw) {
    int i = blockIdx.x * blockDim.x + threadIdx.x;
    if (i >= NN * 16) return;
    int n = i >> 4;
    int j = i & 15;
    float ew = 1.0f / (1.0f + expf(-esw[n]));
    if (j == 0) {
        g_W[i] = 1.0f - ew;
        return;
    }
    float lw = 1.0f / (1.0f + expf(-lsw[n]));
    int k = j - 1;
    g_W[i] = ew * lw * loc_w[n * KK + k] + ew * (1.0f - lw) * nbr_w[n * KK + k];
}

// ---------------- kernel: smoothed residual params -> g_UV ----------------
// u[c] = A_s * cos(P_s)  (multiplies sin(w t)),  v[c] = A_s * sin(P_s)
__global__ void k_uv(const float* __restrict__ amp,
                     const float* __restrict__ ph,
                     const int* __restrict__ idx,
                     const float* __restrict__ nbr_w) {
    int i = blockIdx.x * blockDim.x + threadIdx.x;
    if (i >= NN * NCC) return;
    int n = i / NCC;
    int c = i - n * NCC;
    float sa = 0.0f, ss = 0.0f, sc = 0.0f;
#pragma unroll
    for (int k = 0; k < KK; k++) {
        int m = idx[n * KK + k];
        float w = nbr_w[n * KK + k];
        sa += w * amp[m * NCC + c];
        float p = ph[m * NCC + c];
        float s, co;
        sincosf(p, &s, &co);
        ss += w * s;
        sc += w * co;
    }
    float A = 0.8f * amp[i] + 0.2f * sa;
    float P = 0.8f * ph[i] + 0.2f * atan2f(ss, sc);
    float sp, cp;
    sincosf(P, &sp, &cp);
    g_UV[n * 10 + c] = A * cp;
    g_UV[n * 10 + 5 + c] = A * sp;
}

// ---------------- kernel: harmonic table -> g_tab ----------------
__global__ void k_tab(const float* __restrict__ tv, const float* __restrict__ per) {
    int i = blockIdx.x * blockDim.x + threadIdx.x;
    if (i >= NCC * TT) return;
    int c = i / TT;
    int t = i - c * TT;
    float p = fminf(fmaxf(per[c], 15.0f), 350.0f);
    float arg = 6.283185307179586f * tv[t] / p;
    float s, co;
    sincosf(arg, &s, &co);
    g_tab[i] = s;
    g_tab[NCC * TT + i] = co;
}

// ---------------- main kernel: TMA row-gather + fused output ----------------
extern __shared__ float s_buf[];  // 2 * 16 rows * 400 floats = 51200 B dynamic

__global__ void __launch_bounds__(128, 1)
k_main(const int* __restrict__ idx,
       const float* __restrict__ coff,
       const float* __restrict__ ltr,
       const float* __restrict__ tv,
       float* __restrict__ out) {
    __shared__ __align__(8) unsigned long long s_mbar[2];
    __shared__ int   s_idx[GG][KK];
    __shared__ float s_W[GG][16];
    __shared__ float s_UV[GG][10];

    int tid = threadIdx.x;
    int n0 = blockIdx.x * GG;

    if (tid < GG * KK) s_idx[tid / KK][tid % KK] = idx[n0 * KK + tid];
    if (tid < GG * 16) s_W[tid >> 4][tid & 15] = g_W[n0 * 16 + tid];
    if (tid < GG * 10) s_UV[tid / 10][tid % 10] = g_UV[n0 * 10 + tid];

    uint32_t mbar0 = smem_u32(&s_mbar[0]);
    uint32_t bufb  = smem_u32(s_buf);
    if (tid == 0) {
        mbar_init(mbar0, 1);
        mbar_init(mbar0 + 8, 1);
        asm volatile("fence.proxy.async.shared::cta;" ::: "memory");
    }

    // per-thread register-resident harmonic table + time values
    float4 st[NCC], ct[NCC], tv4;
    bool act = (tid < T4);
    if (act) {
#pragma unroll
        for (int c = 0; c < NCC; c++) {
            st[c] = reinterpret_cast<const float4*>(g_tab + c * TT)[tid];
            ct[c] = reinterpret_cast<const float4*>(g_tab + NCC * TT + c * TT)[tid];
        }
        tv4 = reinterpret_cast<const float4*>(tv)[tid];
    }
    __syncthreads();

    // stage-issue helper (thread 0 only)
    auto issue = [&](int s) {
        uint32_t dst = bufb + (uint32_t)(s & 1) * STAGEBYTES;
        uint32_t mb  = mbar0 + (uint32_t)(s & 1) * 8;
        mbar_expect_tx(mb, STAGEBYTES);
        // row 0: self
        bulk_g2s(dst, g_emd + (size_t)(n0 + s) * TT, ROWBYTES, mb);
#pragma unroll
        for (int k = 0; k < KK; k++) {
            bulk_g2s(dst + (uint32_t)(k + 1) * ROWBYTES,
                     g_emd + (size_t)s_idx[s][k] * TT, ROWBYTES, mb);
        }
    };

    if (tid == 0) issue(0);

    for (int i = 0; i < GG; i++) {
        if (tid == 0 && i + 1 < GG) issue(i + 1);
        mbar_wait(mbar0 + (uint32_t)(i & 1) * 8, (uint32_t)((i >> 1) & 1));

        if (act) {
            int n = n0 + i;
            const float4* rows =
                reinterpret_cast<const float4*>(s_buf + (size_t)(i & 1) * (ROWS * TT));
            float w[16];
#pragma unroll
            for (int j = 0; j < 16; j++) w[j] = s_W[i][j];

            float4 acc = make_float4(0.f, 0.f, 0.f, 0.f);
#pragma unroll
            for (int j = 0; j < 16; j++) {
                float4 r = rows[j * T4 + tid];
                acc.x = fmaf(w[j], r.x, acc.x);
                acc.y = fmaf(w[j], r.y, acc.y);
                acc.z = fmaf(w[j], r.z, acc.z);
                acc.w = fmaf(w[j], r.w, acc.w);
            }
            // residual harmonics: u*sin(wt) + v*cos(wt)
#pragma unroll
            for (int c = 0; c < NCC; c++) {
                float u = s_UV[i][c], v = s_UV[i][5 + c];
                acc.x = fmaf(u, st[c].x, fmaf(v, ct[c].x, acc.x));
                acc.y = fmaf(u, st[c].y, fmaf(v, ct[c].y, acc.y));
                acc.z = fmaf(u, st[c].z, fmaf(v, ct[c].z, acc.z));
                acc.w = fmaf(u, st[c].w, fmaf(v, ct[c].w, acc.w));
            }
            float off = coff[n], tr = ltr[n];
            acc.x += fmaf(tr, tv4.x, off);
            acc.y += fmaf(tr, tv4.y, off);
            acc.z += fmaf(tr, tv4.z, off);
            acc.w += fmaf(tr, tv4.w, off);
            reinterpret_cast<float4*>(out + (size_t)n * TT)[tid] = acc;
        }
        __syncthreads();  // empty-barrier: buffer (i&1) safe to refill at i+2
    }
}

// ---------------- launch ----------------
extern "C" void kernel_launch(void* const* d_in, const int* in_sizes, int n_in,
                              void* d_out, int out_size) {
    const float* tv   = (const float*)d_in[0];   // time_vector [400]
    const float* coff = (const float*)d_in[1];   // constant_offset [N]
    const float* ltr  = (const float*)d_in[2];   // linear_trend [N]
    const float* emd  = (const float*)d_in[3];   // emd_seasonal [N,4,T]
    const int*   idx  = (const int*)  d_in[4];   // neighbor_indices [N,K]
    const float* nw   = (const float*)d_in[5];   // neighbor_weights [N,K]
    const float* lwv  = (const float*)d_in[6];   // local_weights [N,K]
    const float* amp  = (const float*)d_in[7];   // residual_amplitudes [N,5]
    const float* ph   = (const float*)d_in[8];   // residual_phases [N,5]
    const float* per  = (const float*)d_in[9];   // residual_periods [5]
    const float* esw  = (const float*)d_in[10];  // emd_spatial_weights [N]
    const float* lsw  = (const float*)d_in[11];  // local_spatial_weights [N]
    float* out = (float*)d_out;

    k_tab<<<(NCC * TT + 255) / 256, 256>>>(tv, per);
    k_weights<<<(NN * 16 + 255) / 256, 256>>>(nw, lwv, esw, lsw);
    k_uv<<<(NN * NCC + 255) / 256, 256>>>(amp, ph, idx, nw);
    k_emdsum<<<(NN * T4 + 255) / 256, 256>>>(emd);

    cudaFuncSetAttribute(k_main, cudaFuncAttributeMaxDynamicSharedMemorySize,
                         2 * STAGEBYTES);
    k_main<<<NN / GG, 128, 2 * STAGEBYTES>>>(idx, coff, ltr, tv, out);
}

// round 2
// speedup vs baseline: 1.3326x; 1.3326x over previous
#include <cuda_runtime.h>
#include <cuda_fp16.h>
#include <cstdint>
#include <math.h>

#define NN 30000
#define KK 15
#define TT 400
#define NCC 5
#define GG 8                      // rows per block in main kernel
#define ROWS 16                   // self + 15 neighbors
#define ROWBYTES (TT * 2)         // 800 B per fp16 row
#define STAGEBYTES (ROWS * ROWBYTES)  // 12800 B
#define T4 (TT / 4)               // 100 chunks of 4 t-values

// ---------------- scratch (device globals: allocation-free) ----------------
__device__ __align__(16) __half g_emd[NN * TT];   // summed EMD signals fp16 (24 MB)
__device__ float g_W[NN * 16];    // [0]=self weight (1-ew), [1..15]=combined nbr weights
__device__ float g_UV[NN * 10];   // u[5] (coeff of sin), v[5] (coeff of cos)
__device__ float g_tab[2 * NCC * TT];  // sin table then cos table (fp32)

// ---------------- helpers ----------------
__device__ __forceinline__ uint32_t smem_u32(const void* p) {
    uint32_t a;
    asm("{ .reg .u64 t; cvta.to.shared.u64 t, %1; cvt.u32.u64 %0, t; }"
        : "=r"(a) : "l"(p));
    return a;
}
__device__ __forceinline__ void mbar_init(uint32_t mbar, uint32_t count) {
    asm volatile("mbarrier.init.shared.b64 [%0], %1;" :: "r"(mbar), "r"(count) : "memory");
}
__device__ __forceinline__ void mbar_expect_tx(uint32_t mbar, uint32_t bytes) {
    asm volatile("mbarrier.arrive.expect_tx.shared.b64 _, [%0], %1;"
                 :: "r"(mbar), "r"(bytes) : "memory");
}
__device__ __forceinline__ void mbar_wait(uint32_t mbar, uint32_t parity) {
    asm volatile(
        "{\n\t"
        ".reg .pred P;\n\t"
        "LAB_WAIT_%=:\n\t"
        "mbarrier.try_wait.parity.acquire.cta.shared::cta.b64 P, [%0], %1, 0x989680;\n\t"
        "@P bra LAB_DONE_%=;\n\t"
        "bra LAB_WAIT_%=;\n\t"
        "LAB_DONE_%=:\n\t"
        "}"
        :: "r"(mbar), "r"(parity) : "memory");
}
__device__ __forceinline__ void bulk_g2s(uint32_t dst, const void* src,
                                         uint32_t bytes, uint32_t mbar) {
    asm volatile(
        "cp.async.bulk.shared::cluster.global.mbarrier::complete_tx::bytes "
        "[%0], [%1], %2, [%3];"
        :: "r"(dst), "l"(src), "r"(bytes), "r"(mbar) : "memory");
}

// ---------------- fused pre-pass: emdsum(fp16) + weights + uv + tab ----------
#define EMD_WORK  (NN * (TT / 8))            // 1,500,000 (8 t-values per thread)
#define NB_EMD    ((EMD_WORK + 255) / 256)   // 5860
#define NB_W      ((NN * 16 + 255) / 256)    // 1875
#define NB_UV     ((NN * NCC + 255) / 256)   // 586
#define NB_TAB    ((NCC * TT + 255) / 256)   // 8
#define NB_PRE    (NB_EMD + NB_W + NB_UV + NB_TAB)

__global__ void __launch_bounds__(256)
k_pre(const float* __restrict__ emd,
      const float* __restrict__ nbr_w,
      const float* __restrict__ loc_w,
      const float* __restrict__ esw,
      const float* __restrict__ lsw,
      const float* __restrict__ amp,
      const float* __restrict__ ph,
      const int*   __restrict__ idx,
      const float* __restrict__ tv,
      const float* __restrict__ per) {
    int b = blockIdx.x;
    if (b < NB_EMD) {
        // ---- sum 4 EMD components, write fp16 ----
        int i = b * 256 + threadIdx.x;
        if (i >= EMD_WORK) return;
        int n = i / (TT / 8);
        int t8 = i - n * (TT / 8);           // 0..49, covers t = 8*t8 .. 8*t8+7
        const float4* base = reinterpret_cast<const float4*>(emd + (size_t)n * 4 * TT);
        float r[8];
#pragma unroll
        for (int e = 0; e < 8; e++) r[e] = 0.0f;
#pragma unroll
        for (int c = 0; c < 4; c++) {
            float4 a = base[c * T4 + 2 * t8];
            float4 bb = base[c * T4 + 2 * t8 + 1];
            r[0] += a.x;  r[1] += a.y;  r[2] += a.z;  r[3] += a.w;
            r[4] += bb.x; r[5] += bb.y; r[6] += bb.z; r[7] += bb.w;
        }
        __half2 h[4];
#pragma unroll
        for (int e = 0; e < 4; e++)
            h[e] = __floats2half2_rn(r[2 * e], r[2 * e + 1]);
        reinterpret_cast<uint4*>(g_emd + (size_t)n * TT)[t8] =
            *reinterpret_cast<uint4*>(h);
        return;
    }
    b -= NB_EMD;
    if (b < NB_W) {
        // ---- combined spatial weights ----
        int i = b * 256 + threadIdx.x;
        if (i >= NN * 16) return;
        int n = i >> 4;
        int j = i & 15;
        float ew = 1.0f / (1.0f + expf(-esw[n]));
        if (j == 0) { g_W[i] = 1.0f - ew; return; }
        float lw = 1.0f / (1.0f + expf(-lsw[n]));
        int k = j - 1;
        g_W[i] = ew * lw * loc_w[n * KK + k] + ew * (1.0f - lw) * nbr_w[n * KK + k];
        return;
    }
    b -= NB_W;
    if (b < NB_UV) {
        // ---- smoothed residual params -> u,v ----
        int i = b * 256 + threadIdx.x;
        if (i >= NN * NCC) return;
        int n = i / NCC;
        int c = i - n * NCC;
        float sa = 0.0f, ss = 0.0f, sc = 0.0f;
#pragma unroll
        for (int k = 0; k < KK; k++) {
            int m = idx[n * KK + k];
            float w = nbr_w[n * KK + k];
            sa += w * amp[m * NCC + c];
            float p = ph[m * NCC + c];
            float s, co;
            sincosf(p, &s, &co);
            ss += w * s;
            sc += w * co;
        }
        float A = 0.8f * amp[i] + 0.2f * sa;
        float P = 0.8f * ph[i] + 0.2f * atan2f(ss, sc);
        float sp, cp;
        sincosf(P, &sp, &cp);
        g_UV[n * 10 + c] = A * cp;
        g_UV[n * 10 + 5 + c] = A * sp;
        return;
    }
    b -= NB_UV;
    {
        // ---- harmonic sin/cos table ----
        int i = b * 256 + threadIdx.x;
        if (i >= NCC * TT) return;
        int c = i / TT;
        int t = i - c * TT;
        float p = fminf(fmaxf(per[c], 15.0f), 350.0f);
        float arg = 6.283185307179586f * tv[t] / p;
        float s, co;
        sincosf(arg, &s, &co);
        g_tab[i] = s;
        g_tab[NCC * TT + i] = co;
    }
}

// ---------------- main kernel: TMA fp16 row-gather + fused output ----------
extern __shared__ __align__(16) __half s_buf[];  // 2 * 16 rows * 400 halves = 25600 B

__global__ void __launch_bounds__(128)
k_main(const int* __restrict__ idx,
       const float* __restrict__ coff,
       const float* __restrict__ ltr,
       const float* __restrict__ tv,
       float* __restrict__ out) {
    __shared__ __align__(8) unsigned long long s_mbar[2];
    __shared__ int   s_idx[GG][KK];
    __shared__ float s_W[GG][16];
    __shared__ float s_UV[GG][10];

    int tid = threadIdx.x;
    int n0 = blockIdx.x * GG;

    if (tid < GG * KK) s_idx[tid / KK][tid % KK] = idx[n0 * KK + tid];
    if (tid < GG * 16) s_W[tid >> 4][tid & 15] = g_W[n0 * 16 + tid];
    if (tid < GG * 10) s_UV[tid / 10][tid % 10] = g_UV[n0 * 10 + tid];

    uint32_t mbar0 = smem_u32(&s_mbar[0]);
    uint32_t bufb  = smem_u32(s_buf);
    if (tid == 0) {
        mbar_init(mbar0, 1);
        mbar_init(mbar0 + 8, 1);
        asm volatile("fence.proxy.async.shared::cta;" ::: "memory");
    }

    // per-thread register-resident harmonic table + time values (fp32)
    float4 st[NCC], ct[NCC], tv4;
    bool act = (tid < T4);
    if (act) {
#pragma unroll
        for (int c = 0; c < NCC; c++) {
            st[c] = reinterpret_cast<const float4*>(g_tab + c * TT)[tid];
            ct[c] = reinterpret_cast<const float4*>(g_tab + NCC * TT + c * TT)[tid];
        }
        tv4 = reinterpret_cast<const float4*>(tv)[tid];
    }
    __syncthreads();

    auto issue = [&](int s) {
        uint32_t dst = bufb + (uint32_t)(s & 1) * STAGEBYTES;
        uint32_t mb  = mbar0 + (uint32_t)(s & 1) * 8;
        mbar_expect_tx(mb, STAGEBYTES);
        bulk_g2s(dst, g_emd + (size_t)(n0 + s) * TT, ROWBYTES, mb);  // self row
#pragma unroll
        for (int k = 0; k < KK; k++) {
            bulk_g2s(dst + (uint32_t)(k + 1) * ROWBYTES,
                     g_emd + (size_t)s_idx[s][k] * TT, ROWBYTES, mb);
        }
    };

    if (tid == 0) issue(0);

    for (int i = 0; i < GG; i++) {
        if (tid == 0 && i + 1 < GG) issue(i + 1);
        mbar_wait(mbar0 + (uint32_t)(i & 1) * 8, (uint32_t)((i >> 1) & 1));

        if (act) {
            int n = n0 + i;
            // each row is 200 half2; thread covers half2 indices 2*tid, 2*tid+1
            const __half2* rows =
                reinterpret_cast<const __half2*>(s_buf + (size_t)(i & 1) * (ROWS * TT));
            float w[16];
#pragma unroll
            for (int j = 0; j < 16; j++) w[j] = s_W[i][j];

            float4 acc = make_float4(0.f, 0.f, 0.f, 0.f);
#pragma unroll
            for (int j = 0; j < 16; j++) {
                // 8-byte LDS: two half2
                uint2 raw = *reinterpret_cast<const uint2*>(rows + j * 200 + 2 * tid);
                __half2 h0 = *reinterpret_cast<__half2*>(&raw.x);
                __half2 h1 = *reinterpret_cast<__half2*>(&raw.y);
                float2 lo = __half22float2(h0);
                float2 hi = __half22float2(h1);
                acc.x = fmaf(w[j], lo.x, acc.x);
                acc.y = fmaf(w[j], lo.y, acc.y);
                acc.z = fmaf(w[j], hi.x, acc.z);
                acc.w = fmaf(w[j], hi.y, acc.w);
            }
            // residual harmonics: u*sin(wt) + v*cos(wt)
#pragma unroll
            for (int c = 0; c < NCC; c++) {
                float u = s_UV[i][c], v = s_UV[i][5 + c];
                acc.x = fmaf(u, st[c].x, fmaf(v, ct[c].x, acc.x));
                acc.y = fmaf(u, st[c].y, fmaf(v, ct[c].y, acc.y));
                acc.z = fmaf(u, st[c].z, fmaf(v, ct[c].z, acc.z));
                acc.w = fmaf(u, st[c].w, fmaf(v, ct[c].w, acc.w));
            }
            float off = coff[n], tr = ltr[n];
            acc.x += fmaf(tr, tv4.x, off);
            acc.y += fmaf(tr, tv4.y, off);
            acc.z += fmaf(tr, tv4.z, off);
            acc.w += fmaf(tr, tv4.w, off);
            reinterpret_cast<float4*>(out + (size_t)n * TT)[tid] = acc;
        }
        __syncthreads();  // buffer (i&1) safe to refill at stage i+2
    }
}

// ---------------- launch ----------------
extern "C" void kernel_launch(void* const* d_in, const int* in_sizes, int n_in,
                              void* d_out, int out_size) {
    const float* tv   = (const float*)d_in[0];
    const float* coff = (const float*)d_in[1];
    const float* ltr  = (const float*)d_in[2];
    const float* emd  = (const float*)d_in[3];
    const int*   idx  = (const int*)  d_in[4];
    const float* nw   = (const float*)d_in[5];
    const float* lwv  = (const float*)d_in[6];
    const float* amp  = (const float*)d_in[7];
    const float* ph   = (const float*)d_in[8];
    const float* per  = (const float*)d_in[9];
    const float* esw  = (const float*)d_in[10];
    const float* lsw  = (const float*)d_in[11];
    float* out = (float*)d_out;

    k_pre<<<NB_PRE, 256>>>(emd, nw, lwv, esw, lsw, amp, ph, idx, tv, per);

    cudaFuncSetAttribute(k_main, cudaFuncAttributeMaxDynamicSharedMemorySize,
                         2 * STAGEBYTES);
    k_main<<<NN / GG, 128, 2 * STAGEBYTES>>>(idx, coff, ltr, tv, out);
}

// round 3
// speedup vs baseline: 1.3533x; 1.0155x over previous
#include <cuda_runtime.h>
#include <cuda_bf16.h>
#include <cstdint>
#include <math.h>

#define NN 30000
#define KK 15
#define TT 400
#define NCC 5
#define GG 8                      // rows per block in main kernel
#define ROWS 16                   // self + 15 neighbors
#define ROWBYTES (TT * 2)         // 800 B per bf16 row
#define STAGEBYTES (ROWS * ROWBYTES)  // 12800 B
#define T4 (TT / 4)               // 100 chunks of 4 t-values

// ---------------- scratch (device globals: allocation-free) ----------------
__device__ __align__(16) __nv_bfloat16 g_emd[NN * TT];  // summed EMD signals bf16 (24 MB)
__device__ float g_W[NN * 16];    // [0]=self weight (1-ew), [1..15]=combined nbr weights
__device__ float g_UV[NN * 10];   // u[5] (coeff of sin), v[5] (coeff of cos)
__device__ float g_tab[2 * NCC * TT];  // sin table then cos table (fp32)

// ---------------- helpers ----------------
__device__ __forceinline__ uint32_t smem_u32(const void* p) {
    uint32_t a;
    asm("{ .reg .u64 t; cvta.to.shared.u64 t, %1; cvt.u32.u64 %0, t; }"
        : "=r"(a) : "l"(p));
    return a;
}
__device__ __forceinline__ void mbar_init(uint32_t mbar, uint32_t count) {
    asm volatile("mbarrier.init.shared.b64 [%0], %1;" :: "r"(mbar), "r"(count) : "memory");
}
__device__ __forceinline__ void mbar_expect_tx(uint32_t mbar, uint32_t bytes) {
    asm volatile("mbarrier.arrive.expect_tx.shared.b64 _, [%0], %1;"
                 :: "r"(mbar), "r"(bytes) : "memory");
}
__device__ __forceinline__ void mbar_wait(uint32_t mbar, uint32_t parity) {
    asm volatile(
        "{\n\t"
        ".reg .pred P;\n\t"
        "LAB_WAIT_%=:\n\t"
        "mbarrier.try_wait.parity.acquire.cta.shared::cta.b64 P, [%0], %1, 0x989680;\n\t"
        "@P bra LAB_DONE_%=;\n\t"
        "bra LAB_WAIT_%=;\n\t"
        "LAB_DONE_%=:\n\t"
        "}"
        :: "r"(mbar), "r"(parity) : "memory");
}
__device__ __forceinline__ void bulk_g2s(uint32_t dst, const void* src,
                                         uint32_t bytes, uint32_t mbar) {
    asm volatile(
        "cp.async.bulk.shared::cluster.global.mbarrier::complete_tx::bytes "
        "[%0], [%1], %2, [%3];"
        :: "r"(dst), "l"(src), "r"(bytes), "r"(mbar) : "memory");
}
// bf16 (in low / high 16 bits of u) -> fp32, pure ALU ops
__device__ __forceinline__ float bf_lo(uint32_t u) { return __uint_as_float(u << 16); }
__device__ __forceinline__ float bf_hi(uint32_t u) { return __uint_as_float(u & 0xFFFF0000u); }

// ---------------- fused pre-pass: emdsum(bf16) + weights + uv + tab ----------
#define EMD_WORK  (NN * (TT / 8))            // 1,500,000 (8 t-values per thread)
#define NB_EMD    ((EMD_WORK + 255) / 256)
#define NB_W      ((NN * 16 + 255) / 256)
#define NB_UV     ((NN * NCC + 255) / 256)
#define NB_TAB    ((NCC * TT + 255) / 256)
#define NB_PRE    (NB_EMD + NB_W + NB_UV + NB_TAB)

__global__ void __launch_bounds__(256)
k_pre(const float* __restrict__ emd,
      const float* __restrict__ nbr_w,
      const float* __restrict__ loc_w,
      const float* __restrict__ esw,
      const float* __restrict__ lsw,
      const float* __restrict__ amp,
      const float* __restrict__ ph,
      const int*   __restrict__ idx,
      const float* __restrict__ tv,
      const float* __restrict__ per) {
    int b = blockIdx.x;
    if (b < NB_EMD) {
        // ---- sum 4 EMD components, write bf16 ----
        int i = b * 256 + threadIdx.x;
        if (i >= EMD_WORK) return;
        int n = i / (TT / 8);
        int t8 = i - n * (TT / 8);
        const float4* base = reinterpret_cast<const float4*>(emd + (size_t)n * 4 * TT);
        float r[8];
#pragma unroll
        for (int e = 0; e < 8; e++) r[e] = 0.0f;
#pragma unroll
        for (int c = 0; c < 4; c++) {
            float4 a = base[c * T4 + 2 * t8];
            float4 bb = base[c * T4 + 2 * t8 + 1];
            r[0] += a.x;  r[1] += a.y;  r[2] += a.z;  r[3] += a.w;
            r[4] += bb.x; r[5] += bb.y; r[6] += bb.z; r[7] += bb.w;
        }
        __nv_bfloat162 h[4];
#pragma unroll
        for (int e = 0; e < 4; e++)
            h[e] = __floats2bfloat162_rn(r[2 * e], r[2 * e + 1]);
        reinterpret_cast<uint4*>(g_emd + (size_t)n * TT)[t8] =
            *reinterpret_cast<uint4*>(h);
        return;
    }
    b -= NB_EMD;
    if (b < NB_W) {
        int i = b * 256 + threadIdx.x;
        if (i >= NN * 16) return;
        int n = i >> 4;
        int j = i & 15;
        float ew = 1.0f / (1.0f + expf(-esw[n]));
        if (j == 0) { g_W[i] = 1.0f - ew; return; }
        float lw = 1.0f / (1.0f + expf(-lsw[n]));
        int k = j - 1;
        g_W[i] = ew * lw * loc_w[n * KK + k] + ew * (1.0f - lw) * nbr_w[n * KK + k];
        return;
    }
    b -= NB_W;
    if (b < NB_UV) {
        int i = b * 256 + threadIdx.x;
        if (i >= NN * NCC) return;
        int n = i / NCC;
        int c = i - n * NCC;
        float sa = 0.0f, ss = 0.0f, sc = 0.0f;
#pragma unroll
        for (int k = 0; k < KK; k++) {
            int m = idx[n * KK + k];
            float w = nbr_w[n * KK + k];
            sa += w * amp[m * NCC + c];
            float p = ph[m * NCC + c];
            float s, co;
            sincosf(p, &s, &co);
            ss += w * s;
            sc += w * co;
        }
        float A = 0.8f * amp[i] + 0.2f * sa;
        float P = 0.8f * ph[i] + 0.2f * atan2f(ss, sc);
        float sp, cp;
        sincosf(P, &sp, &cp);
        g_UV[n * 10 + c] = A * cp;
        g_UV[n * 10 + 5 + c] = A * sp;
        return;
    }
    b -= NB_UV;
    {
        int i = b * 256 + threadIdx.x;
        if (i >= NCC * TT) return;
        int c = i / TT;
        int t = i - c * TT;
        float p = fminf(fmaxf(per[c], 15.0f), 350.0f);
        float arg = 6.283185307179586f * tv[t] / p;
        float s, co;
        sincosf(arg, &s, &co);
        g_tab[i] = s;
        g_tab[NCC * TT + i] = co;
    }
}

// ---------------- main kernel: TMA bf16 row-gather + fused output ----------
extern __shared__ __align__(16) __nv_bfloat16 s_buf[];  // 2 * 12800 B

__global__ void __launch_bounds__(128)
k_main(const int* __restrict__ idx,
       const float* __restrict__ coff,
       const float* __restrict__ ltr,
       const float* __restrict__ tv,
       float* __restrict__ out) {
    __shared__ __align__(8) unsigned long long s_mbar[2];
    __shared__ int   s_idx[GG][KK];
    __shared__ float s_W[GG][16];
    __shared__ float s_UV[GG][10];

    int tid = threadIdx.x;
    int n0 = blockIdx.x * GG;

    if (tid < GG * KK) s_idx[tid / KK][tid % KK] = idx[n0 * KK + tid];
    if (tid < GG * 16) s_W[tid >> 4][tid & 15] = g_W[n0 * 16 + tid];
    if (tid < GG * 10) s_UV[tid / 10][tid % 10] = g_UV[n0 * 10 + tid];

    uint32_t mbar0 = smem_u32(&s_mbar[0]);
    uint32_t bufb  = smem_u32(s_buf);
    if (tid == 0) {
        mbar_init(mbar0, 1);
        mbar_init(mbar0 + 8, 1);
        asm volatile("fence.proxy.async.shared::cta;" ::: "memory");
    }

    // per-thread register-resident harmonic table + time values (fp32)
    float4 st[NCC], ct[NCC], tv4;
    bool act = (tid < T4);
    if (act) {
#pragma unroll
        for (int c = 0; c < NCC; c++) {
            st[c] = reinterpret_cast<const float4*>(g_tab + c * TT)[tid];
            ct[c] = reinterpret_cast<const float4*>(g_tab + NCC * TT + c * TT)[tid];
        }
        tv4 = reinterpret_cast<const float4*>(tv)[tid];
    }
    __syncthreads();

    auto issue = [&](int s) {
        uint32_t dst = bufb + (uint32_t)(s & 1) * STAGEBYTES;
        uint32_t mb  = mbar0 + (uint32_t)(s & 1) * 8;
        mbar_expect_tx(mb, STAGEBYTES);
        bulk_g2s(dst, g_emd + (size_t)(n0 + s) * TT, ROWBYTES, mb);  // self row
#pragma unroll
        for (int k = 0; k < KK; k++) {
            bulk_g2s(dst + (uint32_t)(k + 1) * ROWBYTES,
                     g_emd + (size_t)s_idx[s][k] * TT, ROWBYTES, mb);
        }
    };

    if (tid == 0) issue(0);

    for (int i = 0; i < GG; i++) {
        if (tid == 0 && i + 1 < GG) issue(i + 1);
        mbar_wait(mbar0 + (uint32_t)(i & 1) * 8, (uint32_t)((i >> 1) & 1));

        if (act) {
            int n = n0 + i;
            const uint32_t* rows = reinterpret_cast<const uint32_t*>(
                s_buf + (size_t)(i & 1) * (ROWS * TT));
            float w[16];
#pragma unroll
            for (int j = 0; j < 16; j++) w[j] = s_W[i][j];

            // init acc with harmonics + linear part
            float off = coff[n], tr = ltr[n];
            float4 acc;
            acc.x = fmaf(tr, tv4.x, off);
            acc.y = fmaf(tr, tv4.y, off);
            acc.z = fmaf(tr, tv4.z, off);
            acc.w = fmaf(tr, tv4.w, off);
#pragma unroll
            for (int c = 0; c < NCC; c++) {
                float u = s_UV[i][c], v = s_UV[i][5 + c];
                acc.x = fmaf(u, st[c].x, fmaf(v, ct[c].x, acc.x));
                acc.y = fmaf(u, st[c].y, fmaf(v, ct[c].y, acc.y));
                acc.z = fmaf(u, st[c].z, fmaf(v, ct[c].z, acc.z));
                acc.w = fmaf(u, st[c].w, fmaf(v, ct[c].w, acc.w));
            }
            // gather: 16 rows, bf16 -> fp32 via ALU shifts
#pragma unroll
            for (int j = 0; j < 16; j++) {
                uint2 raw = *reinterpret_cast<const uint2*>(rows + j * 200 + 2 * tid);
                acc.x = fmaf(w[j], bf_lo(raw.x), acc.x);
                acc.y = fmaf(w[j], bf_hi(raw.x), acc.y);
                acc.z = fmaf(w[j], bf_lo(raw.y), acc.z);
                acc.w = fmaf(w[j], bf_hi(raw.y), acc.w);
            }
            reinterpret_cast<float4*>(out + (size_t)n * TT)[tid] = acc;
        }
        __syncthreads();  // buffer (i&1) safe to refill at stage i+2
    }
}

// ---------------- launch ----------------
extern "C" void kernel_launch(void* const* d_in, const int* in_sizes, int n_in,
                              void* d_out, int out_size) {
    const float* tv   = (const float*)d_in[0];
    const float* coff = (const float*)d_in[1];
    const float* ltr  = (const float*)d_in[2];
    const float* emd  = (const float*)d_in[3];
    const int*   idx  = (const int*)  d_in[4];
    const float* nw   = (const float*)d_in[5];
    const float* lwv  = (const float*)d_in[6];
    const float* amp  = (const float*)d_in[7];
    const float* ph   = (const float*)d_in[8];
    const float* per  = (const float*)d_in[9];
    const float* esw  = (const float*)d_in[10];
    const float* lsw  = (const float*)d_in[11];
    float* out = (float*)d_out;

    k_pre<<<NB_PRE, 256>>>(emd, nw, lwv, esw, lsw, amp, ph, idx, tv, per);

    cudaFuncSetAttribute(k_main, cudaFuncAttributeMaxDynamicSharedMemorySize,
                         2 * STAGEBYTES);
    k_main<<<NN / GG, 128, 2 * STAGEBYTES>>>(idx, coff, ltr, tv, out);
}